// round 14
// baseline (speedup 1.0000x reference)
#include <cuda_runtime.h>
#include <cuda_bf16.h>

// Laplacian-pyramid L1 loss, 5 levels, (32,3,512,512) fp32.
// pyr(in)-pyr(tg) == pyr(in-tg); reflect padding is scale-consistent so the
// upsample needs only a 1-halo down tile. Even/odd deinterleave keeps smem
// unit-stride. R12: L0 uses 128x64 rectangular tiles (dynamic smem) to cut
// halo redundancy and halve block/barrier count on the dominant level.

#define BC 96
#define NLVL 5

__device__ __align__(16) float g_scratch[BC * (256*256 + 128*128 + 64*64)];
__device__ double g_sums[NLVL];          // static zero-init; reset by tail kernel
__device__ unsigned int g_ticket = 0;

__device__ __forceinline__ int refl(int t, int n) {
    if (t < 0)  return -t;
    if (t >= n) return 2*n - 2 - t;
    return t;
}
__device__ __forceinline__ float wt(int i) {
    return (i == 0 || i == 4) ? 1.0f : ((i == 2) ? 6.0f : 4.0f);
}
__device__ __forceinline__ float4 ld4(const float* p) {
    return *reinterpret_cast<const float4*>(p);
}
__device__ __forceinline__ void st4(float* p, float4 v) {
    *reinterpret_cast<float4*>(p) = v;
}
__device__ __forceinline__ float2 ld2(const float* p) {
    return *reinterpret_cast<const float2*>(p);
}
__device__ __forceinline__ void st2(float* p, float2 v) {
    *reinterpret_cast<float2*>(p) = v;
}

__device__ __forceinline__ void block_reduce_atomic(float v, int lvl, float* sred) {
    const int tid = threadIdx.x;
#pragma unroll
    for (int o = 16; o; o >>= 1) v += __shfl_down_sync(0xffffffffu, v, o);
    if ((tid & 31) == 0) sred[tid >> 5] = v;
    __syncthreads();
    if (tid < 16) {
        float x = (tid < (int)(blockDim.x >> 5)) ? sred[tid] : 0.f;
#pragma unroll
        for (int o = 8; o; o >>= 1) x += __shfl_down_sync(0xffffu, x, o);
        if (tid == 0) atomicAdd(&g_sums[lvl], (double)x);
    }
    __syncthreads();
}

// ============== rectangular 128x64 tile kernel (level 0) ==============
template <bool DIFF>
__global__ __launch_bounds__(512)
void lvl_rect(const float* __restrict__ a, const float* __restrict__ b,
              int dstOff, int H, int lvl, int tilesRow)
{
    constexpr int TX = 128, TY = 64, NT = 512;
    constexpr int DT  = TY + 8;       // 72 rows
    constexpr int DW  = TX + 8;       // 136 cols
    constexpr int DCW = DW / 4;       // 34 f4 chunks/row
    constexpr int PE  = TX/2 + 8;     // 72: sdE/sdO pitch
    constexpr int HT  = TY/2 + 2;     // 34 down rows (+halo)
    constexpr int HP  = TX/2 + 4;     // 68: st/sdn pitch
    constexpr int HC  = HP / 4;       // 17
    constexpr int HIY = TY/2, WCX = TX/8;   // 32, 16

    extern __shared__ __align__(16) float smem[];
    float* sdE = smem;                  // DT*PE
    float* sdO = sdE + DT * PE;         // DT*PE
    float* st  = sdO + DT * PE;         // DT*HP
    float* sdn = st  + DT * HP;         // HT*HP
    float* sred = sdn + HT * HP;        // 16

    const int W = H, h = H >> 1;
    const int tid = threadIdx.x;
    const int ty = blockIdx.x / tilesRow, tx = blockIdx.x - ty * tilesRow;
    const int bc = blockIdx.y;
    const int y0 = ty * TY, x0 = tx * TX;
    const int r0 = y0 >> 1,  c0 = x0 >> 1;

    const float* sa = a + (size_t)bc * H * W;
    const float* sb = DIFF ? b + (size_t)bc * H * W : nullptr;

    // ---- load diff tile, deinterleave even/odd columns ----
    const bool interior = (y0 >= 4) & (y0 + TY + 4 <= H) &
                          (x0 >= 4) & (x0 + TX + 4 <= W);
    if (interior) {
        const float* pa = sa + (size_t)(y0 - 4) * W + (x0 - 4);
        const float* pb = DIFF ? sb + (size_t)(y0 - 4) * W + (x0 - 4) : nullptr;
        for (int it = tid; it < DT * DCW; it += NT) {
            int row = it / DCW, col = it - row * DCW;
            size_t g = (size_t)row * W + 4 * col;
            float4 v;
            if (DIFF) {
                float4 x1 = __ldcs(reinterpret_cast<const float4*>(pa + g));
                float4 x2 = __ldcs(reinterpret_cast<const float4*>(pb + g));
                v = make_float4(x1.x - x2.x, x1.y - x2.y, x1.z - x2.z, x1.w - x2.w);
            } else {
                v = ld4(pa + g);
            }
            st2(sdE + row * PE + 2 * col, make_float2(v.x, v.z));
            st2(sdO + row * PE + 2 * col, make_float2(v.y, v.w));
        }
    } else {
        for (int it = tid; it < DT * DCW; it += NT) {
            int row = it / DCW, col = it - row * DCW;
            int gy  = y0 - 4 + row;
            int gx0 = x0 - 4 + 4 * col;
            float4 v;
            if (gy >= 0 && gy < H && gx0 >= 0 && gx0 + 3 < W) {
                size_t g = (size_t)gy * W + gx0;
                v = ld4(sa + g);
                if (DIFF) {
                    float4 w = ld4(sb + g);
                    v.x -= w.x; v.y -= w.y; v.z -= w.z; v.w -= w.w;
                }
            } else {
                int yy = refl(gy, H);
                float t[4];
#pragma unroll
                for (int k = 0; k < 4; k++) {
                    int xx = refl(gx0 + k, W);
                    size_t g = (size_t)yy * W + xx;
                    t[k] = sa[g];
                    if (DIFF) t[k] -= sb[g];
                }
                v = make_float4(t[0], t[1], t[2], t[3]);
            }
            st2(sdE + row * PE + 2 * col, make_float2(v.x, v.z));
            st2(sdO + row * PE + 2 * col, make_float2(v.y, v.w));
        }
    }
    __syncthreads();

    // ---- horizontal gauss ----
    for (int it = tid; it < DT * HC; it += NT) {
        int r = it / HC, k = it - r * HC;
        const float* Er = sdE + r * PE + 4 * k;
        const float* Or = sdO + r * PE + 4 * k;
        float4 Ea = ld4(Er), Eb = ld4(Er + 4);
        float4 Oa = ld4(Or), Ob = ld4(Or + 4);
        float4 o;
        o.x = Ea.x + 6.f*Ea.y + Ea.z + 4.f*(Oa.x + Oa.y);
        o.y = Ea.y + 6.f*Ea.z + Ea.w + 4.f*(Oa.y + Oa.z);
        o.z = Ea.z + 6.f*Ea.w + Eb.x + 4.f*(Oa.z + Oa.w);
        o.w = Ea.w + 6.f*Eb.x + Eb.y + 4.f*(Oa.w + Ob.x);
        st4(st + r * HP + 4 * k, o);
    }
    __syncthreads();

    // ---- vertical gauss, stride 2 ----
    for (int it = tid; it < HT * HC; it += NT) {
        int r = it / HC, ck = it - r * HC;
        const float* base = st + (2 * r) * HP + 4 * ck;
        float4 r0v = ld4(base),        r1v = ld4(base + HP),
               r2v = ld4(base + 2*HP), r3v = ld4(base + 3*HP),
               r4v = ld4(base + 4*HP);
        float4 o;
        o.x = (r0v.x + 4.f*r1v.x + 6.f*r2v.x + 4.f*r3v.x + r4v.x) * (1.f/256.f);
        o.y = (r0v.y + 4.f*r1v.y + 6.f*r2v.y + 4.f*r3v.y + r4v.y) * (1.f/256.f);
        o.z = (r0v.z + 4.f*r1v.z + 6.f*r2v.z + 4.f*r3v.z + r4v.z) * (1.f/256.f);
        o.w = (r0v.w + 4.f*r1v.w + 6.f*r2v.w + 4.f*r3v.w + r4v.w) * (1.f/256.f);
        st4(sdn + r * HP + 4 * ck, o);
    }
    __syncthreads();

    // ---- write interior down tile (512 items = 1/thread) ----
    {
        float* gdn = g_scratch + dstOff + (size_t)bc * h * h;
        int r = tid >> 4, ck = tid & 15;
        const float* s = sdn + (r + 1) * HP + 4 * ck + 1;
        st4(gdn + (size_t)(r0 + r) * h + c0 + 4 * ck,
            make_float4(s[0], s[1], s[2], s[3]));
    }

    // ---- direct 2D upsample from sdn + |d - up| (1024 items = 2/thread) ----
    float lsum = 0.0f;
    for (int it = tid; it < HIY * (TX/4); it += NT) {
        const int r = it >> 5;        // 0..31 row-pair
        const int j = it & 31;        // 0..31 x-quad
        const float* base = sdn + r * HP + 2 * j;
        float2 A0 = ld2(base),          B0 = ld2(base + 2);
        float2 A1 = ld2(base + HP),     B1 = ld2(base + HP + 2);
        float2 A2 = ld2(base + 2*HP),   B2 = ld2(base + 2*HP + 2);

        float h0A = A0.x + 6.f*A0.y + B0.x, h0B = A0.y + 6.f*B0.x + B0.y;
        float h0C = 4.f*(A0.y + B0.x),      h0D = 4.f*(B0.x + B0.y);
        float h1A = A1.x + 6.f*A1.y + B1.x, h1B = A1.y + 6.f*B1.x + B1.y;
        float h1C = 4.f*(A1.y + B1.x),      h1D = 4.f*(B1.x + B1.y);
        float h2A = A2.x + 6.f*A2.y + B2.x, h2B = A2.y + 6.f*B2.x + B2.y;
        float h2C = 4.f*(A2.y + B2.x),      h2D = 4.f*(B2.x + B2.y);

        constexpr float i64 = 1.f / 64.f;
        float u00 = (h0A + 6.f*h1A + h2A) * i64;
        float u01 = (h0C + 6.f*h1C + h2C) * i64;
        float u02 = (h0B + 6.f*h1B + h2B) * i64;
        float u03 = (h0D + 6.f*h1D + h2D) * i64;
        float u10 = (h1A + h2A) * (4.f * i64);
        float u11 = (h1C + h2C) * (4.f * i64);
        float u12 = (h1B + h2B) * (4.f * i64);
        float u13 = (h1D + h2D) * (4.f * i64);

        const int offE = (2*r + 4) * PE + 2 * j + 2;
        float2 dE0 = ld2(sdE + offE),      dO0 = ld2(sdO + offE);
        float2 dE1 = ld2(sdE + offE + PE), dO1 = ld2(sdO + offE + PE);

        lsum += fabsf(dE0.x - u00) + fabsf(dO0.x - u01)
              + fabsf(dE0.y - u02) + fabsf(dO0.y - u03)
              + fabsf(dE1.x - u10) + fabsf(dO1.x - u11)
              + fabsf(dE1.y - u12) + fabsf(dO1.y - u13);
    }
    block_reduce_atomic(lsum, lvl, sred);
}

// Dynamic smem bytes for lvl_rect<128,64>
#define RECT_SMEM_BYTES ((2*72*72 + 72*68 + 34*68 + 16) * 4)

// ---------------- tiled kernel: levels 1..2 (TILE=64, 512 thr) ----------------
template <bool DIFF>
__global__ __launch_bounds__(512)
void lvl_kernel(const float* __restrict__ a, const float* __restrict__ b,
                int srcOff, int dstOff, int H, int lvl, int tilesRow)
{
    constexpr int TILE = 64;
    constexpr int DT = 72;
    constexpr int DC = 18;
    constexpr int PE = 40;
    constexpr int HT = 34;
    constexpr int HP = 36;
    constexpr int HI = 32;
    constexpr int NT = 512;

    __shared__ __align__(16) float sdE[DT * PE];
    __shared__ __align__(16) float sdO[DT * PE];
    __shared__ __align__(16) float st [DT * HP];
    __shared__ __align__(16) float sdn[HT * HP];
    __shared__ float sred[16];

    const int W = H, h = H >> 1;
    const int tid = threadIdx.x;
    const int ty = blockIdx.x / tilesRow, tx = blockIdx.x - ty * tilesRow;
    const int bc = blockIdx.y;
    const int y0 = ty * TILE, x0 = tx * TILE;
    const int r0 = y0 >> 1,  c0 = x0 >> 1;

    const float* sa = DIFF ? a + (size_t)bc * H * W
                           : g_scratch + srcOff + (size_t)bc * H * W;
    const float* sb = DIFF ? b + (size_t)bc * H * W : nullptr;

    const bool interior = (y0 >= 4) & (y0 + TILE + 4 <= H) &
                          (x0 >= 4) & (x0 + TILE + 4 <= W);
    if (interior) {
        const float* pa = sa + (size_t)(y0 - 4) * W + (x0 - 4);
        const float* pb = DIFF ? sb + (size_t)(y0 - 4) * W + (x0 - 4) : nullptr;
        for (int it = tid; it < DT * DC; it += NT) {
            int row = it / DC, col = it - row * DC;
            size_t g = (size_t)row * W + 4 * col;
            float4 v;
            if (DIFF) {
                float4 x1 = __ldcs(reinterpret_cast<const float4*>(pa + g));
                float4 x2 = __ldcs(reinterpret_cast<const float4*>(pb + g));
                v = make_float4(x1.x - x2.x, x1.y - x2.y, x1.z - x2.z, x1.w - x2.w);
            } else {
                v = ld4(pa + g);
            }
            st2(sdE + row * PE + 2 * col, make_float2(v.x, v.z));
            st2(sdO + row * PE + 2 * col, make_float2(v.y, v.w));
        }
    } else {
        for (int it = tid; it < DT * DC; it += NT) {
            int row = it / DC, col = it - row * DC;
            int gy  = y0 - 4 + row;
            int gx0 = x0 - 4 + 4 * col;
            float4 v;
            if (gy >= 0 && gy < H && gx0 >= 0 && gx0 + 3 < W) {
                size_t g = (size_t)gy * W + gx0;
                v = ld4(sa + g);
                if (DIFF) {
                    float4 w = ld4(sb + g);
                    v.x -= w.x; v.y -= w.y; v.z -= w.z; v.w -= w.w;
                }
            } else {
                int yy = refl(gy, H);
                float t[4];
#pragma unroll
                for (int k = 0; k < 4; k++) {
                    int xx = refl(gx0 + k, W);
                    size_t g = (size_t)yy * W + xx;
                    t[k] = sa[g];
                    if (DIFF) t[k] -= sb[g];
                }
                v = make_float4(t[0], t[1], t[2], t[3]);
            }
            st2(sdE + row * PE + 2 * col, make_float2(v.x, v.z));
            st2(sdO + row * PE + 2 * col, make_float2(v.y, v.w));
        }
    }
    __syncthreads();

    for (int it = tid; it < DT * 9; it += NT) {
        int r = it / 9, k = it - r * 9;
        const float* Er = sdE + r * PE + 4 * k;
        const float* Or = sdO + r * PE + 4 * k;
        float4 Ea = ld4(Er), Eb = ld4(Er + 4);
        float4 Oa = ld4(Or), Ob = ld4(Or + 4);
        float4 o;
        o.x = Ea.x + 6.f*Ea.y + Ea.z + 4.f*(Oa.x + Oa.y);
        o.y = Ea.y + 6.f*Ea.z + Ea.w + 4.f*(Oa.y + Oa.z);
        o.z = Ea.z + 6.f*Ea.w + Eb.x + 4.f*(Oa.z + Oa.w);
        o.w = Ea.w + 6.f*Eb.x + Eb.y + 4.f*(Oa.w + Ob.x);
        st4(st + r * HP + 4 * k, o);
    }
    __syncthreads();

    for (int it = tid; it < HT * 9; it += NT) {
        int r = it / 9, ck = it - r * 9;
        const float* base = st + (2 * r) * HP + 4 * ck;
        float4 r0v = ld4(base),        r1v = ld4(base + HP),
               r2v = ld4(base + 2*HP), r3v = ld4(base + 3*HP),
               r4v = ld4(base + 4*HP);
        float4 o;
        o.x = (r0v.x + 4.f*r1v.x + 6.f*r2v.x + 4.f*r3v.x + r4v.x) * (1.f/256.f);
        o.y = (r0v.y + 4.f*r1v.y + 6.f*r2v.y + 4.f*r3v.y + r4v.y) * (1.f/256.f);
        o.z = (r0v.z + 4.f*r1v.z + 6.f*r2v.z + 4.f*r3v.z + r4v.z) * (1.f/256.f);
        o.w = (r0v.w + 4.f*r1v.w + 6.f*r2v.w + 4.f*r3v.w + r4v.w) * (1.f/256.f);
        st4(sdn + r * HP + 4 * ck, o);
    }
    __syncthreads();

    {
        float* gdn = g_scratch + dstOff + (size_t)bc * h * h;
        for (int it = tid; it < HI * 8; it += NT) {
            int r = it >> 3, ck = it & 7;
            const float* s = sdn + (r + 1) * HP + 4 * ck + 1;
            st4(gdn + (size_t)(r0 + r) * h + c0 + 4 * ck,
                make_float4(s[0], s[1], s[2], s[3]));
        }
    }

    float lsum = 0.0f;
    {
        const int r = tid >> 4;
        const int j = tid & 15;
        const float* base = sdn + r * HP + 2 * j;
        float2 A0 = ld2(base),          B0 = ld2(base + 2);
        float2 A1 = ld2(base + HP),     B1 = ld2(base + HP + 2);
        float2 A2 = ld2(base + 2*HP),   B2 = ld2(base + 2*HP + 2);

        float h0A = A0.x + 6.f*A0.y + B0.x, h0B = A0.y + 6.f*B0.x + B0.y;
        float h0C = 4.f*(A0.y + B0.x),      h0D = 4.f*(B0.x + B0.y);
        float h1A = A1.x + 6.f*A1.y + B1.x, h1B = A1.y + 6.f*B1.x + B1.y;
        float h1C = 4.f*(A1.y + B1.x),      h1D = 4.f*(B1.x + B1.y);
        float h2A = A2.x + 6.f*A2.y + B2.x, h2B = A2.y + 6.f*B2.x + B2.y;
        float h2C = 4.f*(A2.y + B2.x),      h2D = 4.f*(B2.x + B2.y);

        constexpr float i64 = 1.f / 64.f;
        float u00 = (h0A + 6.f*h1A + h2A) * i64;
        float u01 = (h0C + 6.f*h1C + h2C) * i64;
        float u02 = (h0B + 6.f*h1B + h2B) * i64;
        float u03 = (h0D + 6.f*h1D + h2D) * i64;
        float u10 = (h1A + h2A) * (4.f * i64);
        float u11 = (h1C + h2C) * (4.f * i64);
        float u12 = (h1B + h2B) * (4.f * i64);
        float u13 = (h1D + h2D) * (4.f * i64);

        const int offE = (2*r + 4) * PE + 2 * j + 2;
        float2 dE0 = ld2(sdE + offE),      dO0 = ld2(sdO + offE);
        float2 dE1 = ld2(sdE + offE + PE), dO1 = ld2(sdO + offE + PE);

        lsum += fabsf(dE0.x - u00) + fabsf(dO0.x - u01)
              + fabsf(dE0.y - u02) + fabsf(dO0.y - u03)
              + fabsf(dE1.x - u10) + fabsf(dO1.x - u11)
              + fabsf(dE1.y - u12) + fabsf(dO1.y - u13);
    }
    block_reduce_atomic(lsum, lvl, sred);
}

// -------- fused levels 3+4 + final reduction: one block per bc-plane --------
__global__ __launch_bounds__(512)
void tail_kernel(int srcOff, float* __restrict__ out)
{
    __shared__ __align__(16) float sa  [64 * 64];
    __shared__ __align__(16) float st3 [64 * 34];
    __shared__ __align__(16) float sdn3[34 * 34];
    __shared__ __align__(16) float st4m[32 * 18];
    __shared__ __align__(16) float sdn4[18 * 18];
    __shared__ float sred3[16];
    __shared__ float sred4[16];

    const int tid = threadIdx.x;
    constexpr int NT = 512;
    const int bc = blockIdx.x;

    const float* g = g_scratch + srcOff + (size_t)bc * 64 * 64;
    for (int idx = tid; idx < 64 * 64 / 4; idx += NT)
        st4(sa + 4*idx, ld4(g + 4*idx));
    __syncthreads();

    for (int idx = tid; idx < 64 * 34; idx += NT) {
        int y = idx / 34, dc = idx - y * 34;
        const float* row = sa + y * 64;
        float acc;
        if (dc >= 2 && dc <= 31) {
            const float* p = row + 2*dc - 4;
            acc = p[0] + 4.f*p[1] + 6.f*p[2] + 4.f*p[3] + p[4];
        } else {
            acc = 0.f;
#pragma unroll
            for (int j = 0; j < 5; j++) acc += wt(j) * row[refl(2*dc - 4 + j, 64)];
        }
        st3[idx] = acc;
    }
    __syncthreads();

    for (int idx = tid; idx < 34 * 34; idx += NT) {
        int dr = idx / 34, dc = idx - dr * 34;
        float acc;
        if (dr >= 2 && dr <= 31) {
            const float* p = st3 + (2*dr - 4) * 34 + dc;
            acc = p[0] + 4.f*p[34] + 6.f*p[68] + 4.f*p[102] + p[136];
        } else {
            acc = 0.f;
#pragma unroll
            for (int i = 0; i < 5; i++) acc += wt(i) * st3[refl(2*dr - 4 + i, 64) * 34 + dc];
        }
        sdn3[idx] = acc * (1.f/256.f);
    }
    __syncthreads();

    float l3 = 0.f;
    {
        const int r = tid >> 4;
        const int j = tid & 15;
        const float* base = sdn3 + r * 34 + 2 * j;
        float2 A0 = ld2(base),        B0 = ld2(base + 2);
        float2 A1 = ld2(base + 34),   B1 = ld2(base + 36);
        float2 A2 = ld2(base + 68),   B2 = ld2(base + 70);

        float h0A = A0.x + 6.f*A0.y + B0.x, h0B = A0.y + 6.f*B0.x + B0.y;
        float h0C = 4.f*(A0.y + B0.x),      h0D = 4.f*(B0.x + B0.y);
        float h1A = A1.x + 6.f*A1.y + B1.x, h1B = A1.y + 6.f*B1.x + B1.y;
        float h1C = 4.f*(A1.y + B1.x),      h1D = 4.f*(B1.x + B1.y);
        float h2A = A2.x + 6.f*A2.y + B2.x, h2B = A2.y + 6.f*B2.x + B2.y;
        float h2C = 4.f*(A2.y + B2.x),      h2D = 4.f*(B2.x + B2.y);

        constexpr float i64 = 1.f / 64.f;
        float4 d0 = ld4(sa + (2*r) * 64 + 4*j);
        float4 d1 = ld4(sa + (2*r + 1) * 64 + 4*j);
        l3 += fabsf(d0.x - (h0A + 6.f*h1A + h2A) * i64)
            + fabsf(d0.y - (h0C + 6.f*h1C + h2C) * i64)
            + fabsf(d0.z - (h0B + 6.f*h1B + h2B) * i64)
            + fabsf(d0.w - (h0D + 6.f*h1D + h2D) * i64)
            + fabsf(d1.x - (h1A + h2A) * (4.f*i64))
            + fabsf(d1.y - (h1C + h2C) * (4.f*i64))
            + fabsf(d1.z - (h1B + h2B) * (4.f*i64))
            + fabsf(d1.w - (h1D + h2D) * (4.f*i64));
    }
    for (int idx = tid; idx < 32 * 18; idx += NT) {
        int y = idx / 18, dc = idx - y * 18;
        const float* row = sdn3 + 35 + y * 34;
        float acc;
        if (dc >= 2 && dc <= 15) {
            const float* p = row + 2*dc - 4;
            acc = p[0] + 4.f*p[1] + 6.f*p[2] + 4.f*p[3] + p[4];
        } else {
            acc = 0.f;
#pragma unroll
            for (int j = 0; j < 5; j++) acc += wt(j) * row[refl(2*dc - 4 + j, 32)];
        }
        st4m[idx] = acc;
    }
    __syncthreads();

    for (int idx = tid; idx < 18 * 18; idx += NT) {
        int dr = idx / 18, dc = idx - dr * 18;
        float acc;
        if (dr >= 2 && dr <= 15) {
            const float* p = st4m + (2*dr - 4) * 18 + dc;
            acc = p[0] + 4.f*p[18] + 6.f*p[36] + 4.f*p[54] + p[72];
        } else {
            acc = 0.f;
#pragma unroll
            for (int i = 0; i < 5; i++) acc += wt(i) * st4m[refl(2*dr - 4 + i, 32) * 18 + dc];
        }
        sdn4[idx] = acc * (1.f/256.f);
    }
    __syncthreads();

    float l4 = 0.f;
    if (tid < 16 * 8) {
        const int r = tid >> 3;
        const int j = tid & 7;
        const float* base = sdn4 + r * 18 + 2 * j;
        float2 A0 = ld2(base),        B0 = ld2(base + 2);
        float2 A1 = ld2(base + 18),   B1 = ld2(base + 20);
        float2 A2 = ld2(base + 36),   B2 = ld2(base + 38);

        float h0A = A0.x + 6.f*A0.y + B0.x, h0B = A0.y + 6.f*B0.x + B0.y;
        float h0C = 4.f*(A0.y + B0.x),      h0D = 4.f*(B0.x + B0.y);
        float h1A = A1.x + 6.f*A1.y + B1.x, h1B = A1.y + 6.f*B1.x + B1.y;
        float h1C = 4.f*(A1.y + B1.x),      h1D = 4.f*(B1.x + B1.y);
        float h2A = A2.x + 6.f*A2.y + B2.x, h2B = A2.y + 6.f*B2.x + B2.y;
        float h2C = 4.f*(A2.y + B2.x),      h2D = 4.f*(B2.x + B2.y);

        constexpr float i64 = 1.f / 64.f;
        const float* s0 = sdn3 + 35 + (2*r) * 34 + 4*j;
        const float* s1 = s0 + 34;
        l4 += fabsf(s0[0] - (h0A + 6.f*h1A + h2A) * i64)
            + fabsf(s0[1] - (h0C + 6.f*h1C + h2C) * i64)
            + fabsf(s0[2] - (h0B + 6.f*h1B + h2B) * i64)
            + fabsf(s0[3] - (h0D + 6.f*h1D + h2D) * i64)
            + fabsf(s1[0] - (h1A + h2A) * (4.f*i64))
            + fabsf(s1[1] - (h1C + h2C) * (4.f*i64))
            + fabsf(s1[2] - (h1B + h2B) * (4.f*i64))
            + fabsf(s1[3] - (h1D + h2D) * (4.f*i64));
    }

#pragma unroll
    for (int o = 16; o; o >>= 1) {
        l3 += __shfl_down_sync(0xffffffffu, l3, o);
        l4 += __shfl_down_sync(0xffffffffu, l4, o);
    }
    if ((tid & 31) == 0) { sred3[tid >> 5] = l3; sred4[tid >> 5] = l4; }
    __syncthreads();
    if (tid < 16) {
        float x3 = sred3[tid], x4 = sred4[tid];
#pragma unroll
        for (int o = 8; o; o >>= 1) {
            x3 += __shfl_down_sync(0xffffu, x3, o);
            x4 += __shfl_down_sync(0xffffu, x4, o);
        }
        if (tid == 0) {
            atomicAdd(&g_sums[3], (double)x3);
            atomicAdd(&g_sums[4], (double)x4);
        }
    }
    __syncthreads();

    if (tid == 0) {
        __threadfence();
        unsigned int t = atomicAdd(&g_ticket, 1u);
        if (t == gridDim.x - 1) {
            const double inv[NLVL] = {
                1.0 / ((double)BC * 512 * 512),
                1.0 / ((double)BC * 256 * 256),
                1.0 / ((double)BC * 128 * 128),
                1.0 / ((double)BC *  64 *  64),
                1.0 / ((double)BC *  32 *  32)
            };
            double tot = 0.0;
#pragma unroll
            for (int l = 0; l < NLVL; l++) tot += g_sums[l] * inv[l];
            out[0] = (float)tot;
#pragma unroll
            for (int l = 0; l < NLVL; l++) g_sums[l] = 0.0;
            g_ticket = 0;
            __threadfence();
        }
    }
}

extern "C" void kernel_launch(void* const* d_in, const int* in_sizes, int n_in,
                              void* d_out, int out_size) {
    const float* input  = (const float*)d_in[0];
    const float* target = (const float*)d_in[1];
    float* out = (float*)d_out;

    const int OFF0 = 0;
    const int OFF1 = BC * 256*256;
    const int OFF2 = OFF1 + BC * 128*128;

    // opt-in dynamic smem for the rect kernel (idempotent; capture-safe)
    cudaFuncSetAttribute(lvl_rect<true>,
                         cudaFuncAttributeMaxDynamicSharedMemorySize,
                         RECT_SMEM_BYTES);

    // L0: H=512, 128x64 tiles -> 4 x 8 = 32 tiles/plane
    lvl_rect<true><<<dim3(32, BC), 512, RECT_SMEM_BYTES>>>(input, target, OFF0, 512, 0, 4);
    // L1: H=256, T64, 4x4
    lvl_kernel<false><<<dim3(16, BC), 512>>>(nullptr, nullptr, OFF0, OFF1, 256, 1, 4);
    // L2: H=128, T64, 2x2
    lvl_kernel<false><<<dim3(4,  BC), 512>>>(nullptr, nullptr, OFF1, OFF2, 128, 2, 2);
    tail_kernel<<<BC, 512>>>(OFF2, out);
}

// round 16
// speedup vs baseline: 1.1363x; 1.1363x over previous
#include <cuda_runtime.h>
#include <cuda_bf16.h>

// Laplacian-pyramid L1 loss, 5 levels, (32,3,512,512) fp32.
// pyr(in)-pyr(tg) == pyr(in-tg); reflect padding is scale-consistent so the
// upsample needs only a 1-halo down tile. Even/odd deinterleave keeps smem
// unit-stride. R13: back to T64 tiles everywhere (R12 rect regressed);
// lvl_kernel at 384 threads -> 5 blocks/SM (94% occ) to hide barrier drains.

#define BC 96
#define NLVL 5

__device__ __align__(16) float g_scratch[BC * (256*256 + 128*128 + 64*64)];
__device__ double g_sums[NLVL];          // static zero-init; reset by tail kernel
__device__ unsigned int g_ticket = 0;

__device__ __forceinline__ int refl(int t, int n) {
    if (t < 0)  return -t;
    if (t >= n) return 2*n - 2 - t;
    return t;
}
__device__ __forceinline__ float wt(int i) {
    return (i == 0 || i == 4) ? 1.0f : ((i == 2) ? 6.0f : 4.0f);
}
__device__ __forceinline__ float4 ld4(const float* p) {
    return *reinterpret_cast<const float4*>(p);
}
__device__ __forceinline__ void st4(float* p, float4 v) {
    *reinterpret_cast<float4*>(p) = v;
}
__device__ __forceinline__ float2 ld2(const float* p) {
    return *reinterpret_cast<const float2*>(p);
}
__device__ __forceinline__ void st2(float* p, float2 v) {
    *reinterpret_cast<float2*>(p) = v;
}

__device__ __forceinline__ void block_reduce_atomic(float v, int lvl, float* sred) {
    const int tid = threadIdx.x;
#pragma unroll
    for (int o = 16; o; o >>= 1) v += __shfl_down_sync(0xffffffffu, v, o);
    if ((tid & 31) == 0) sred[tid >> 5] = v;
    __syncthreads();
    if (tid < 16) {
        float x = (tid < (int)(blockDim.x >> 5)) ? sred[tid] : 0.f;
#pragma unroll
        for (int o = 8; o; o >>= 1) x += __shfl_down_sync(0xffffu, x, o);
        if (tid == 0) atomicAdd(&g_sums[lvl], (double)x);
    }
    __syncthreads();
}

// ---------------- tiled kernel: levels 0..2 (TILE=64, 384 thr) ----------------
template <bool DIFF>
__global__ __launch_bounds__(384)
void lvl_kernel(const float* __restrict__ a, const float* __restrict__ b,
                int srcOff, int dstOff, int H, int lvl, int tilesRow)
{
    constexpr int TILE = 64;
    constexpr int DT = 72;            // full-res rows (tile + 4-halo)
    constexpr int DC = 18;            // float4 chunks per full-res row
    constexpr int PE = 40;            // pitch of sdE/sdO
    constexpr int HT = 34;            // down rows (+1-halo)
    constexpr int HP = 36;            // st/sdn pitch
    constexpr int HI = 32;            // down interior
    constexpr int NT = 384;

    __shared__ __align__(16) float sdE[DT * PE];
    __shared__ __align__(16) float sdO[DT * PE];
    __shared__ __align__(16) float st [DT * HP];
    __shared__ __align__(16) float sdn[HT * HP];
    __shared__ float sred[16];

    const int W = H, h = H >> 1;
    const int tid = threadIdx.x;
    const int ty = blockIdx.x / tilesRow, tx = blockIdx.x - ty * tilesRow;
    const int bc = blockIdx.y;
    const int y0 = ty * TILE, x0 = tx * TILE;
    const int r0 = y0 >> 1,  c0 = x0 >> 1;

    const float* sa = DIFF ? a + (size_t)bc * H * W
                           : g_scratch + srcOff + (size_t)bc * H * W;
    const float* sb = DIFF ? b + (size_t)bc * H * W : nullptr;

    // ---- load diff tile, deinterleave even/odd columns ----
    const bool interior = (y0 >= 4) & (y0 + TILE + 4 <= H) &
                          (x0 >= 4) & (x0 + TILE + 4 <= W);
    if (interior) {
        const float* pa = sa + (size_t)(y0 - 4) * W + (x0 - 4);
        const float* pb = DIFF ? sb + (size_t)(y0 - 4) * W + (x0 - 4) : nullptr;
        for (int it = tid; it < DT * DC; it += NT) {
            int row = it / DC, col = it - row * DC;
            size_t g = (size_t)row * W + 4 * col;
            float4 v;
            if (DIFF) {
                float4 x1 = __ldcs(reinterpret_cast<const float4*>(pa + g));
                float4 x2 = __ldcs(reinterpret_cast<const float4*>(pb + g));
                v = make_float4(x1.x - x2.x, x1.y - x2.y, x1.z - x2.z, x1.w - x2.w);
            } else {
                v = ld4(pa + g);
            }
            st2(sdE + row * PE + 2 * col, make_float2(v.x, v.z));
            st2(sdO + row * PE + 2 * col, make_float2(v.y, v.w));
        }
    } else {
        for (int it = tid; it < DT * DC; it += NT) {
            int row = it / DC, col = it - row * DC;
            int gy  = y0 - 4 + row;
            int gx0 = x0 - 4 + 4 * col;
            float4 v;
            if (gy >= 0 && gy < H && gx0 >= 0 && gx0 + 3 < W) {
                size_t g = (size_t)gy * W + gx0;
                v = ld4(sa + g);
                if (DIFF) {
                    float4 w = ld4(sb + g);
                    v.x -= w.x; v.y -= w.y; v.z -= w.z; v.w -= w.w;
                }
            } else {
                int yy = refl(gy, H);
                float t[4];
#pragma unroll
                for (int k = 0; k < 4; k++) {
                    int xx = refl(gx0 + k, W);
                    size_t g = (size_t)yy * W + xx;
                    t[k] = sa[g];
                    if (DIFF) t[k] -= sb[g];
                }
                v = make_float4(t[0], t[1], t[2], t[3]);
            }
            st2(sdE + row * PE + 2 * col, make_float2(v.x, v.z));
            st2(sdO + row * PE + 2 * col, make_float2(v.y, v.w));
        }
    }
    __syncthreads();

    // ---- horizontal gauss (stride-2 folded into parity arrays) ----
    for (int it = tid; it < DT * 9; it += NT) {
        int r = it / 9, k = it - r * 9;
        const float* Er = sdE + r * PE + 4 * k;
        const float* Or = sdO + r * PE + 4 * k;
        float4 Ea = ld4(Er), Eb = ld4(Er + 4);
        float4 Oa = ld4(Or), Ob = ld4(Or + 4);
        float4 o;
        o.x = Ea.x + 6.f*Ea.y + Ea.z + 4.f*(Oa.x + Oa.y);
        o.y = Ea.y + 6.f*Ea.z + Ea.w + 4.f*(Oa.y + Oa.z);
        o.z = Ea.z + 6.f*Ea.w + Eb.x + 4.f*(Oa.z + Oa.w);
        o.w = Ea.w + 6.f*Eb.x + Eb.y + 4.f*(Oa.w + Ob.x);
        st4(st + r * HP + 4 * k, o);
    }
    __syncthreads();

    // ---- vertical gauss, stride 2 ----
    for (int it = tid; it < HT * 9; it += NT) {
        int r = it / 9, ck = it - r * 9;
        const float* base = st + (2 * r) * HP + 4 * ck;
        float4 r0v = ld4(base),        r1v = ld4(base + HP),
               r2v = ld4(base + 2*HP), r3v = ld4(base + 3*HP),
               r4v = ld4(base + 4*HP);
        float4 o;
        o.x = (r0v.x + 4.f*r1v.x + 6.f*r2v.x + 4.f*r3v.x + r4v.x) * (1.f/256.f);
        o.y = (r0v.y + 4.f*r1v.y + 6.f*r2v.y + 4.f*r3v.y + r4v.y) * (1.f/256.f);
        o.z = (r0v.z + 4.f*r1v.z + 6.f*r2v.z + 4.f*r3v.z + r4v.z) * (1.f/256.f);
        o.w = (r0v.w + 4.f*r1v.w + 6.f*r2v.w + 4.f*r3v.w + r4v.w) * (1.f/256.f);
        st4(sdn + r * HP + 4 * ck, o);
    }
    __syncthreads();

    // ---- write interior down tile (next level source) ----
    {
        float* gdn = g_scratch + dstOff + (size_t)bc * h * h;
        for (int it = tid; it < HI * 8; it += NT) {
            int r = it >> 3, ck = it & 7;
            const float* s = sdn + (r + 1) * HP + 4 * ck + 1;
            st4(gdn + (size_t)(r0 + r) * h + c0 + 4 * ck,
                make_float4(s[0], s[1], s[2], s[3]));
        }
    }

    // ---- direct 2D upsample from sdn + |d - up| (512 items, looped) ----
    float lsum = 0.0f;
    for (int it = tid; it < 512; it += NT) {
        const int r = it >> 4;        // 0..31 row-pair
        const int j = it & 15;        // 0..15 x-quad
        const float* base = sdn + r * HP + 2 * j;
        float2 A0 = ld2(base),          B0 = ld2(base + 2);
        float2 A1 = ld2(base + HP),     B1 = ld2(base + HP + 2);
        float2 A2 = ld2(base + 2*HP),   B2 = ld2(base + 2*HP + 2);

        float h0A = A0.x + 6.f*A0.y + B0.x, h0B = A0.y + 6.f*B0.x + B0.y;
        float h0C = 4.f*(A0.y + B0.x),      h0D = 4.f*(B0.x + B0.y);
        float h1A = A1.x + 6.f*A1.y + B1.x, h1B = A1.y + 6.f*B1.x + B1.y;
        float h1C = 4.f*(A1.y + B1.x),      h1D = 4.f*(B1.x + B1.y);
        float h2A = A2.x + 6.f*A2.y + B2.x, h2B = A2.y + 6.f*B2.x + B2.y;
        float h2C = 4.f*(A2.y + B2.x),      h2D = 4.f*(B2.x + B2.y);

        constexpr float i64 = 1.f / 64.f;
        float u00 = (h0A + 6.f*h1A + h2A) * i64;
        float u01 = (h0C + 6.f*h1C + h2C) * i64;
        float u02 = (h0B + 6.f*h1B + h2B) * i64;
        float u03 = (h0D + 6.f*h1D + h2D) * i64;
        float u10 = (h1A + h2A) * (4.f * i64);
        float u11 = (h1C + h2C) * (4.f * i64);
        float u12 = (h1B + h2B) * (4.f * i64);
        float u13 = (h1D + h2D) * (4.f * i64);

        const int offE = (2*r + 4) * PE + 2 * j + 2;
        float2 dE0 = ld2(sdE + offE),      dO0 = ld2(sdO + offE);
        float2 dE1 = ld2(sdE + offE + PE), dO1 = ld2(sdO + offE + PE);

        lsum += fabsf(dE0.x - u00) + fabsf(dO0.x - u01)
              + fabsf(dE0.y - u02) + fabsf(dO0.y - u03)
              + fabsf(dE1.x - u10) + fabsf(dO1.x - u11)
              + fabsf(dE1.y - u12) + fabsf(dO1.y - u13);
    }
    block_reduce_atomic(lsum, lvl, sred);
}

// -------- fused levels 3+4 + final reduction: one block per bc-plane --------
__global__ __launch_bounds__(512)
void tail_kernel(int srcOff, float* __restrict__ out)
{
    __shared__ __align__(16) float sa  [64 * 64];
    __shared__ __align__(16) float st3 [64 * 34];
    __shared__ __align__(16) float sdn3[34 * 34];
    __shared__ __align__(16) float st4m[32 * 18];
    __shared__ __align__(16) float sdn4[18 * 18];
    __shared__ float sred3[16];
    __shared__ float sred4[16];

    const int tid = threadIdx.x;
    constexpr int NT = 512;
    const int bc = blockIdx.x;

    const float* g = g_scratch + srcOff + (size_t)bc * 64 * 64;
    for (int idx = tid; idx < 64 * 64 / 4; idx += NT)
        st4(sa + 4*idx, ld4(g + 4*idx));
    __syncthreads();

    for (int idx = tid; idx < 64 * 34; idx += NT) {
        int y = idx / 34, dc = idx - y * 34;
        const float* row = sa + y * 64;
        float acc;
        if (dc >= 2 && dc <= 31) {
            const float* p = row + 2*dc - 4;
            acc = p[0] + 4.f*p[1] + 6.f*p[2] + 4.f*p[3] + p[4];
        } else {
            acc = 0.f;
#pragma unroll
            for (int j = 0; j < 5; j++) acc += wt(j) * row[refl(2*dc - 4 + j, 64)];
        }
        st3[idx] = acc;
    }
    __syncthreads();

    for (int idx = tid; idx < 34 * 34; idx += NT) {
        int dr = idx / 34, dc = idx - dr * 34;
        float acc;
        if (dr >= 2 && dr <= 31) {
            const float* p = st3 + (2*dr - 4) * 34 + dc;
            acc = p[0] + 4.f*p[34] + 6.f*p[68] + 4.f*p[102] + p[136];
        } else {
            acc = 0.f;
#pragma unroll
            for (int i = 0; i < 5; i++) acc += wt(i) * st3[refl(2*dr - 4 + i, 64) * 34 + dc];
        }
        sdn3[idx] = acc * (1.f/256.f);
    }
    __syncthreads();

    float l3 = 0.f;
    {
        const int r = tid >> 4;
        const int j = tid & 15;
        const float* base = sdn3 + r * 34 + 2 * j;
        float2 A0 = ld2(base),        B0 = ld2(base + 2);
        float2 A1 = ld2(base + 34),   B1 = ld2(base + 36);
        float2 A2 = ld2(base + 68),   B2 = ld2(base + 70);

        float h0A = A0.x + 6.f*A0.y + B0.x, h0B = A0.y + 6.f*B0.x + B0.y;
        float h0C = 4.f*(A0.y + B0.x),      h0D = 4.f*(B0.x + B0.y);
        float h1A = A1.x + 6.f*A1.y + B1.x, h1B = A1.y + 6.f*B1.x + B1.y;
        float h1C = 4.f*(A1.y + B1.x),      h1D = 4.f*(B1.x + B1.y);
        float h2A = A2.x + 6.f*A2.y + B2.x, h2B = A2.y + 6.f*B2.x + B2.y;
        float h2C = 4.f*(A2.y + B2.x),      h2D = 4.f*(B2.x + B2.y);

        constexpr float i64 = 1.f / 64.f;
        float4 d0 = ld4(sa + (2*r) * 64 + 4*j);
        float4 d1 = ld4(sa + (2*r + 1) * 64 + 4*j);
        l3 += fabsf(d0.x - (h0A + 6.f*h1A + h2A) * i64)
            + fabsf(d0.y - (h0C + 6.f*h1C + h2C) * i64)
            + fabsf(d0.z - (h0B + 6.f*h1B + h2B) * i64)
            + fabsf(d0.w - (h0D + 6.f*h1D + h2D) * i64)
            + fabsf(d1.x - (h1A + h2A) * (4.f*i64))
            + fabsf(d1.y - (h1C + h2C) * (4.f*i64))
            + fabsf(d1.z - (h1B + h2B) * (4.f*i64))
            + fabsf(d1.w - (h1D + h2D) * (4.f*i64));
    }
    for (int idx = tid; idx < 32 * 18; idx += NT) {
        int y = idx / 18, dc = idx - y * 18;
        const float* row = sdn3 + 35 + y * 34;
        float acc;
        if (dc >= 2 && dc <= 15) {
            const float* p = row + 2*dc - 4;
            acc = p[0] + 4.f*p[1] + 6.f*p[2] + 4.f*p[3] + p[4];
        } else {
            acc = 0.f;
#pragma unroll
            for (int j = 0; j < 5; j++) acc += wt(j) * row[refl(2*dc - 4 + j, 32)];
        }
        st4m[idx] = acc;
    }
    __syncthreads();

    for (int idx = tid; idx < 18 * 18; idx += NT) {
        int dr = idx / 18, dc = idx - dr * 18;
        float acc;
        if (dr >= 2 && dr <= 15) {
            const float* p = st4m + (2*dr - 4) * 18 + dc;
            acc = p[0] + 4.f*p[18] + 6.f*p[36] + 4.f*p[54] + p[72];
        } else {
            acc = 0.f;
#pragma unroll
            for (int i = 0; i < 5; i++) acc += wt(i) * st4m[refl(2*dr - 4 + i, 32) * 18 + dc];
        }
        sdn4[idx] = acc * (1.f/256.f);
    }
    __syncthreads();

    float l4 = 0.f;
    if (tid < 16 * 8) {
        const int r = tid >> 3;
        const int j = tid & 7;
        const float* base = sdn4 + r * 18 + 2 * j;
        float2 A0 = ld2(base),        B0 = ld2(base + 2);
        float2 A1 = ld2(base + 18),   B1 = ld2(base + 20);
        float2 A2 = ld2(base + 36),   B2 = ld2(base + 38);

        float h0A = A0.x + 6.f*A0.y + B0.x, h0B = A0.y + 6.f*B0.x + B0.y;
        float h0C = 4.f*(A0.y + B0.x),      h0D = 4.f*(B0.x + B0.y);
        float h1A = A1.x + 6.f*A1.y + B1.x, h1B = A1.y + 6.f*B1.x + B1.y;
        float h1C = 4.f*(A1.y + B1.x),      h1D = 4.f*(B1.x + B1.y);
        float h2A = A2.x + 6.f*A2.y + B2.x, h2B = A2.y + 6.f*B2.x + B2.y;
        float h2C = 4.f*(A2.y + B2.x),      h2D = 4.f*(B2.x + B2.y);

        constexpr float i64 = 1.f / 64.f;
        const float* s0 = sdn3 + 35 + (2*r) * 34 + 4*j;
        const float* s1 = s0 + 34;
        l4 += fabsf(s0[0] - (h0A + 6.f*h1A + h2A) * i64)
            + fabsf(s0[1] - (h0C + 6.f*h1C + h2C) * i64)
            + fabsf(s0[2] - (h0B + 6.f*h1B + h2B) * i64)
            + fabsf(s0[3] - (h0D + 6.f*h1D + h2D) * i64)
            + fabsf(s1[0] - (h1A + h2A) * (4.f*i64))
            + fabsf(s1[1] - (h1C + h2C) * (4.f*i64))
            + fabsf(s1[2] - (h1B + h2B) * (4.f*i64))
            + fabsf(s1[3] - (h1D + h2D) * (4.f*i64));
    }

#pragma unroll
    for (int o = 16; o; o >>= 1) {
        l3 += __shfl_down_sync(0xffffffffu, l3, o);
        l4 += __shfl_down_sync(0xffffffffu, l4, o);
    }
    if ((tid & 31) == 0) { sred3[tid >> 5] = l3; sred4[tid >> 5] = l4; }
    __syncthreads();
    if (tid < 16) {
        float x3 = sred3[tid], x4 = sred4[tid];
#pragma unroll
        for (int o = 8; o; o >>= 1) {
            x3 += __shfl_down_sync(0xffffu, x3, o);
            x4 += __shfl_down_sync(0xffffu, x4, o);
        }
        if (tid == 0) {
            atomicAdd(&g_sums[3], (double)x3);
            atomicAdd(&g_sums[4], (double)x4);
        }
    }
    __syncthreads();

    if (tid == 0) {
        __threadfence();
        unsigned int t = atomicAdd(&g_ticket, 1u);
        if (t == gridDim.x - 1) {
            const double inv[NLVL] = {
                1.0 / ((double)BC * 512 * 512),
                1.0 / ((double)BC * 256 * 256),
                1.0 / ((double)BC * 128 * 128),
                1.0 / ((double)BC *  64 *  64),
                1.0 / ((double)BC *  32 *  32)
            };
            double tot = 0.0;
#pragma unroll
            for (int l = 0; l < NLVL; l++) tot += g_sums[l] * inv[l];
            out[0] = (float)tot;
#pragma unroll
            for (int l = 0; l < NLVL; l++) g_sums[l] = 0.0;
            g_ticket = 0;
            __threadfence();
        }
    }
}

extern "C" void kernel_launch(void* const* d_in, const int* in_sizes, int n_in,
                              void* d_out, int out_size) {
    const float* input  = (const float*)d_in[0];
    const float* target = (const float*)d_in[1];
    float* out = (float*)d_out;

    const int OFF0 = 0;
    const int OFF1 = BC * 256*256;
    const int OFF2 = OFF1 + BC * 128*128;

    lvl_kernel<true ><<<dim3(64, BC), 384>>>(input,  target,  0,    OFF0, 512, 0, 8);
    lvl_kernel<false><<<dim3(16, BC), 384>>>(nullptr, nullptr, OFF0, OFF1, 256, 1, 4);
    lvl_kernel<false><<<dim3(4,  BC), 384>>>(nullptr, nullptr, OFF1, OFF2, 128, 2, 2);
    tail_kernel<<<BC, 512>>>(OFF2, out);
}